// round 1
// baseline (speedup 1.0000x reference)
#include <cuda_runtime.h>

#define RES 512
#define RANKF 8   // floats per texel
#define NTHREADS 256

// Sample one plane bilinearly at (u,v) in [-1,1] and accumulate W[:, wbase:wbase+8] @ f
// into acc0/acc1 (the 8 output accumulators).
__device__ __forceinline__ void sample_accum(
    const float4* __restrict__ plane,   // plane as float4[RES*RES*2]
    float u, float v,
    const float* __restrict__ Wsm,      // [24][8] transposed projection
    int wbase,
    float4& acc0, float4& acc1)
{
    // unnormalize, align_corners=False, border clamp (matches reference op order)
    float x = ((u + 1.0f) * 512.0f - 1.0f) * 0.5f;
    float y = ((v + 1.0f) * 512.0f - 1.0f) * 0.5f;
    x = fminf(fmaxf(x, 0.0f), 511.0f);
    y = fminf(fmaxf(y, 0.0f), 511.0f);

    float x0f = floorf(x);
    float y0f = floorf(y);
    float wx = x - x0f;
    float wy = y - y0f;
    int x0 = (int)x0f;
    int y0 = (int)y0f;
    int x1 = min(x0 + 1, 511);
    int y1 = min(y0 + 1, 511);

    int r0 = y0 << 9;   // y0 * 512
    int r1 = y1 << 9;

    // 4 corners, each 8 floats = 2 float4. Adjacent-x corners are contiguous 64B.
    const float4 a0 = __ldg(plane + (((r0 + x0) << 1) + 0));
    const float4 a1 = __ldg(plane + (((r0 + x0) << 1) + 1));
    const float4 b0 = __ldg(plane + (((r0 + x1) << 1) + 0));
    const float4 b1 = __ldg(plane + (((r0 + x1) << 1) + 1));
    const float4 c0 = __ldg(plane + (((r1 + x0) << 1) + 0));
    const float4 c1 = __ldg(plane + (((r1 + x0) << 1) + 1));
    const float4 d0 = __ldg(plane + (((r1 + x1) << 1) + 0));
    const float4 d1 = __ldg(plane + (((r1 + x1) << 1) + 1));

    float f[8];
    {
        // top = a + wx*(b-a); bot = c + wx*(d-c); f = top + wy*(bot-top)
        float t, bo;
        t  = a0.x + wx * (b0.x - a0.x);  bo = c0.x + wx * (d0.x - c0.x);  f[0] = t + wy * (bo - t);
        t  = a0.y + wx * (b0.y - a0.y);  bo = c0.y + wx * (d0.y - c0.y);  f[1] = t + wy * (bo - t);
        t  = a0.z + wx * (b0.z - a0.z);  bo = c0.z + wx * (d0.z - c0.z);  f[2] = t + wy * (bo - t);
        t  = a0.w + wx * (b0.w - a0.w);  bo = c0.w + wx * (d0.w - c0.w);  f[3] = t + wy * (bo - t);
        t  = a1.x + wx * (b1.x - a1.x);  bo = c1.x + wx * (d1.x - c1.x);  f[4] = t + wy * (bo - t);
        t  = a1.y + wx * (b1.y - a1.y);  bo = c1.y + wx * (d1.y - c1.y);  f[5] = t + wy * (bo - t);
        t  = a1.z + wx * (b1.z - a1.z);  bo = c1.z + wx * (d1.z - c1.z);  f[6] = t + wy * (bo - t);
        t  = a1.w + wx * (b1.w - a1.w);  bo = c1.w + wx * (d1.w - c1.w);  f[7] = t + wy * (bo - t);
    }

    // acc += f[r] * W[:, wbase+r]   (W transposed in smem: row = input feat, 8 outs contiguous)
    #pragma unroll
    for (int r = 0; r < 8; r++) {
        const float s = f[r];
        const float4* wrow = reinterpret_cast<const float4*>(Wsm + ((wbase + r) << 3));
        const float4 w0 = wrow[0];
        const float4 w1 = wrow[1];
        acc0.x += s * w0.x;  acc0.y += s * w0.y;  acc0.z += s * w0.z;  acc0.w += s * w0.w;
        acc1.x += s * w1.x;  acc1.y += s * w1.y;  acc1.z += s * w1.z;  acc1.w += s * w1.w;
    }
}

__global__ void __launch_bounds__(NTHREADS)
geo_encoder_kernel(
    const float*  __restrict__ coords,   // [N,3]
    const float4* __restrict__ pxy,
    const float4* __restrict__ pxz,
    const float4* __restrict__ pyz,
    const float*  __restrict__ Wp,       // [8,24]
    const float*  __restrict__ bp,       // [8]
    float*        __restrict__ out,      // [N,8]
    int n)
{
    __shared__ float Wsm[192];   // transposed: Wsm[k*8+j] = Wp[j*24+k]
    __shared__ float bsm[8];

    const int t = threadIdx.x;
    if (t < 192) Wsm[t] = Wp[(t & 7) * 24 + (t >> 3)];
    if (t < 8)   bsm[t] = bp[t];
    __syncthreads();

    const int i = blockIdx.x * NTHREADS + t;
    if (i >= n) return;

    float cx = coords[3 * i + 0];
    float cy = coords[3 * i + 1];
    float cz = coords[3 * i + 2];
    cx = fminf(fmaxf(cx, -1.0f), 1.0f);
    cy = fminf(fmaxf(cy, -1.0f), 1.0f);
    cz = fminf(fmaxf(cz, -1.0f), 1.0f);

    float4 acc0 = make_float4(bsm[0], bsm[1], bsm[2], bsm[3]);
    float4 acc1 = make_float4(bsm[4], bsm[5], bsm[6], bsm[7]);

    sample_accum(pxy, cx, cy, Wsm,  0, acc0, acc1);   // plane_xy: (x, y)
    sample_accum(pxz, cx, cz, Wsm,  8, acc0, acc1);   // plane_xz: (x, z)
    sample_accum(pyz, cy, cz, Wsm, 16, acc0, acc1);   // plane_yz: (y, z)

    // clip to [-10, 10]
    acc0.x = fminf(fmaxf(acc0.x, -10.0f), 10.0f);
    acc0.y = fminf(fmaxf(acc0.y, -10.0f), 10.0f);
    acc0.z = fminf(fmaxf(acc0.z, -10.0f), 10.0f);
    acc0.w = fminf(fmaxf(acc0.w, -10.0f), 10.0f);
    acc1.x = fminf(fmaxf(acc1.x, -10.0f), 10.0f);
    acc1.y = fminf(fmaxf(acc1.y, -10.0f), 10.0f);
    acc1.z = fminf(fmaxf(acc1.z, -10.0f), 10.0f);
    acc1.w = fminf(fmaxf(acc1.w, -10.0f), 10.0f);

    float4* o = reinterpret_cast<float4*>(out) + (i << 1);
    o[0] = acc0;
    o[1] = acc1;
}

extern "C" void kernel_launch(void* const* d_in, const int* in_sizes, int n_in,
                              void* d_out, int out_size)
{
    const float*  coords = (const float*)d_in[0];
    const float4* pxy    = (const float4*)d_in[1];
    const float4* pxz    = (const float4*)d_in[2];
    const float4* pyz    = (const float4*)d_in[3];
    const float*  Wp     = (const float*)d_in[4];
    const float*  bp     = (const float*)d_in[5];
    float*        out    = (float*)d_out;

    const int n = in_sizes[0] / 3;
    const int blocks = (n + NTHREADS - 1) / NTHREADS;
    geo_encoder_kernel<<<blocks, NTHREADS>>>(coords, pxy, pxz, pyz, Wp, bp, out, n);
}